// round 14
// baseline (speedup 1.0000x reference)
#include <cuda_runtime.h>
#include <cuda_fp16.h>
#include <cstdint>
#include <cstddef>

#define BB 256
#define TT 256
#define II 512
#define HH 1024

#define NTHREADS 128
#define NCTA 256

// ---- loop-phase dynamic smem layout (float offsets) ----
#define L_A      0
#define L_A_BUF  4352                 // A stage: 64 rows x 136 halves (68 floats)
#define L_W16    8704                 // W fp16: 64 x 264 halves = 8448 floats
#define L_XP     17152                // 2 x (64 x 16) floats
#define L_XP_BUF 1024
#define L_BI     19200
#define L_BI_BUF 16
#define SMEM_FLOATS 19232
#define SMEM_BYTES  (SMEM_FLOATS*4)   // 76928 B  (+ ~4.1KB static < 113.5KB/CTA)

// ---- prologue-phase aliased smem layout (temporally disjoint) ----
#define P_A32    0                    // 2 x (128 x 36)
#define P_A32_BUF 4608
#define P_W32    9216                 // 2 x (64 x 36)
#define P_W32_BUF 2304
#define P_A16    13824                // 128 x 40 halves = 2560 floats
#define P_W16    16384                // 64 x 40 halves = 1280 floats -> ends 17664

// ---- persistent device state ----
__device__ __half   g_h[2][BB * HH];                 // double-buffered h (fp16), quarter-blocked rows
__device__ __half   g_wh16[(size_t)TT * HH * HH];    // Wh pre-converted to fp16 (512MB)
__device__ float    g_part[2][4 * 64 * 4096];        // [parity][(qq*64+lh)*4096] fp32
__device__ float    g_xpart[(size_t)TT * BB * HH];   // x@Wx^T fp32, sorted rows
__device__ unsigned g_cnt[3];
__device__ unsigned g_gen[3];
__device__ unsigned g_pflag[4][16];                  // partial producers per quarter/nblk
__device__ unsigned g_hflag[4][4];                   // h reducers per quarter/ks-group

// ---- grid barrier ----
__device__ __forceinline__ void gbar(int idx, unsigned count) {
    __threadfence();
    __syncthreads();
    if (threadIdx.x == 0) {
        volatile unsigned* vg = (volatile unsigned*)&g_gen[idx];
        unsigned g = *vg;
        unsigned old = atomicAdd(&g_cnt[idx], 1u);
        if (old == count - 1) {
            g_cnt[idx] = 0;
            __threadfence();
            *vg = g + 1;
        } else {
            while (*vg == g) {}
            __threadfence();
        }
    }
    __syncthreads();
}

// ---- monotonic flag sync ----
__device__ __forceinline__ void arrive(unsigned* f) {
    __threadfence();
    __syncthreads();
    if (threadIdx.x == 0) atomicAdd(f, 1u);
}
__device__ __forceinline__ void waitflag(unsigned* f, unsigned target) {
    __syncthreads();
    if (threadIdx.x == 0) {
        volatile unsigned* vf = (volatile unsigned*)f;
        while (*vf < target) {}
        __threadfence();
    }
    __syncthreads();
}

// ---- helpers ----
__device__ __forceinline__ void cpa(void* dst, const void* src) {
    uint32_t d = (uint32_t)__cvta_generic_to_shared(dst);
    asm volatile("cp.async.cg.shared.global [%0], [%1], 16;" :: "r"(d), "l"(src));
}
#define CPCOMMIT() asm volatile("cp.async.commit_group;")
#define CPWAIT(n)  asm volatile("cp.async.wait_group %0;" :: "n"(n))

// fp16 mma: m16n8k16, fp32 accum
__device__ __forceinline__ void mma16h(float* c, uint32_t a0, uint32_t a1,
                                       uint32_t a2, uint32_t a3,
                                       uint32_t b0, uint32_t b1) {
    asm volatile(
        "mma.sync.aligned.m16n8k16.row.col.f32.f16.f16.f32 "
        "{%0,%1,%2,%3},{%4,%5,%6,%7},{%8,%9},{%0,%1,%2,%3};"
        : "+f"(c[0]), "+f"(c[1]), "+f"(c[2]), "+f"(c[3])
        : "r"(a0), "r"(a1), "r"(a2), "r"(a3), "r"(b0), "r"(b1));
}

// convert Wh[t] (1M fp32) -> g_wh16[t]
__device__ __forceinline__ void convert_wh(const float* __restrict__ Wh, int t, int tid) {
    const float4* src = (const float4*)(Wh + (size_t)t * HH * HH);
    unsigned short* dst = (unsigned short*)(g_wh16 + (size_t)t * HH * HH);
    for (int i = tid; i < (HH * HH) / 4; i += NTHREADS) {
        float4 f = __ldcg(&src[i]);
        __half2 h0 = __floats2half2_rn(f.x, f.y);
        __half2 h1 = __floats2half2_rn(f.z, f.w);
        uint2 o;
        o.x = *(unsigned*)&h0;
        o.y = *(unsigned*)&h1;
        *(uint2*)(dst + i * 4) = o;
    }
}

// ---- persistent kernel ----
__global__ void __launch_bounds__(NTHREADS, 2)
SequenceModelPadded_kernel(
    const float* __restrict__ inp,        // (B,T,I)
    const void*  __restrict__ slen_raw,   // (B,) int64 OR int32
    const float* __restrict__ Wx,         // (T,H,I)
    const float* __restrict__ Wh,         // (T,H,H)
    const float* __restrict__ bias,       // (T,H)
    const float* __restrict__ Wout,       // (1,H)
    const float* __restrict__ bout,       // (1,)
    float* __restrict__ out)              // (B,1)
{
    extern __shared__ float sm[];
    __shared__ int s_is64;
    __shared__ int s_perm[256];
    __shared__ int s_lorig[256];
    __shared__ int s_lsorted[256];
    __shared__ int s_act[256];

    int tid  = threadIdx.x;
    int bx   = blockIdx.x;
    int qq   = bx >> 6;          // quarter 0..3 (64 batch rows each)
    int lh   = bx & 63;
    int nblk = lh >> 2;          // 0..15 (N tile of 64 cols)
    int ks   = lh & 3;           // 0..3  (K split of 256)

    int lane = tid & 31, warp = tid >> 5;   // 4 warps
    int wm = warp & 1, wn = warp >> 1;      // 2 x 2 warp grid
    int g  = lane >> 2, tg = lane & 3;

    // ---- seq_lengths dtype sniff ----
    if (tid == 0) {
        const unsigned* w = (const unsigned*)slen_raw;
        unsigned z = 0;
        for (int i = 1; i < 256; i += 2) z |= __ldg(&w[i]);
        s_is64 = (z == 0) ? 1 : 0;
    }
    __syncthreads();
    const int is64 = s_is64;

    // ---- stable sort of lengths (descending) ----
    for (int i = tid; i < 256; i += NTHREADS) {
        int L = is64 ? (int)__ldg(&((const int*)slen_raw)[i * 2])
                     : (int)__ldg(&((const int*)slen_raw)[i]);
        s_lorig[i] = L;
    }
    __syncthreads();
    for (int i = tid; i < 256; i += NTHREADS) {
        int L = s_lorig[i];
        int rank = 0;
        for (int j = 0; j < 256; j++) {
            int Lj = s_lorig[j];
            rank += (Lj > L) || (Lj == L && j < i);
        }
        s_perm[rank]    = i;
        s_lsorted[rank] = L;
    }
    __syncthreads();
    // active count per step for OWN quarter (rank r -> quarter r&3, local r>>2)
    for (int t = tid; t < 256; t += NTHREADS) {
        int a = 0;
        for (int rl = 0; rl < 64; rl++)
            a += (s_lsorted[4 * rl + qq] > t) ? 1 : 0;
        s_act[t] = a;
    }
    __syncthreads();
    const int hmax = s_lsorted[qq];   // quarter's max length

    // ---- zero BOTH h buffers (512 uints per CTA) ----
    for (int e = tid; e < 512; e += NTHREADS) {
        ((unsigned*)&g_h[0][0])[bx * 512 + e] = 0u;
        ((unsigned*)&g_h[1][0])[bx * 512 + e] = 0u;
    }

    // ---- reset flags ----
    if (bx == 0 && tid == 0) {
        for (int q = 0; q < 4; q++) {
            for (int i = 0; i < 16; i++) g_pflag[q][i] = 0;
            for (int i = 0; i < 4;  i++) g_hflag[q][i] = 0;
        }
    }

    // ---- Wh -> fp16 conversion for t = bx (staggered vs co-resident pair) ----
    int conv_first = (bx >> 2) & 1;   // pair (b, b+148) differ in this bit
    if (conv_first) convert_wh(Wh, bx, tid);

    // ============================================================
    // PROLOGUE GEMM: xpart[bx, ranks] = x[perm[r], bx] @ Wx[bx]^T
    // One t per CTA. Tile: 2 M-subtiles of 128 x 16 nt of N=64, K=512.
    // 4 warps, warp tile 64x32, fp16 mma (k-chunks of 32).
    // ============================================================
    {
        int t = bx;
        int actp = 0;
        for (int j = 0; j < 256; j++) actp += (s_lsorted[j] > t) ? 1 : 0;
        if (actp > 0) {
            int actpL = (actp + 15) & ~15;
            for (int mh = 0; mh < 2; mh++) {
                if (mh * 128 >= actpL) break;
                for (int nt = 0; nt < 16; nt++) {
                    float acc[4][4][4];
#pragma unroll
                    for (int s = 0; s < 4; s++)
#pragma unroll
                        for (int u = 0; u < 4; u++)
#pragma unroll
                            for (int q = 0; q < 4; q++) acc[s][u][q] = 0.f;

                    {   // chunk 0 fp32 loads
                        float* pa = sm + P_A32;
                        float* pw = sm + P_W32;
#pragma unroll
                        for (int it = 0; it < 8; it++) {
                            int v = tid + NTHREADS * it; int row = v >> 3, seg = v & 7;
                            int rank = mh * 128 + row;
                            if (rank < actpL) {
                                int pr = s_perm[rank];
                                cpa(pa + row * 36 + seg * 4,
                                    inp + (size_t)pr * (TT * II) + (size_t)t * II + seg * 4);
                            }
                        }
#pragma unroll
                        for (int it = 0; it < 4; it++) {
                            int v = tid + NTHREADS * it; int row = v >> 3, seg = v & 7;
                            cpa(pw + row * 36 + seg * 4,
                                Wx + ((size_t)t * HH + nt * 64 + row) * II + seg * 4);
                        }
                        CPCOMMIT();
                    }
                    for (int ch = 0; ch < 16; ch++) {
                        if (ch < 15) {
                            int nb = (ch + 1) & 1;
                            float* pa = sm + P_A32 + nb * P_A32_BUF;
                            float* pw = sm + P_W32 + nb * P_W32_BUF;
                            int ko = (ch + 1) * 32;
#pragma unroll
                            for (int it = 0; it < 8; it++) {
                                int v = tid + NTHREADS * it; int row = v >> 3, seg = v & 7;
                                int rank = mh * 128 + row;
                                if (rank < actpL) {
                                    int pr = s_perm[rank];
                                    cpa(pa + row * 36 + seg * 4,
                                        inp + (size_t)pr * (TT * II) + (size_t)t * II + ko + seg * 4);
                                }
                            }
#pragma unroll
                            for (int it = 0; it < 4; it++) {
                                int v = tid + NTHREADS * it; int row = v >> 3, seg = v & 7;
                                cpa(pw + row * 36 + seg * 4,
                                    Wx + ((size_t)t * HH + nt * 64 + row) * II + ko + seg * 4);
                            }
                            CPCOMMIT();
                            CPWAIT(1);
                        } else {
                            CPWAIT(0);
                        }
                        __syncthreads();
                        // cvt chunk -> fp16 tiles (once per element)
                        {
                            const float* pa = sm + P_A32 + (ch & 1) * P_A32_BUF;
                            const float* pw = sm + P_W32 + (ch & 1) * P_W32_BUF;
                            unsigned short* pa16 = (unsigned short*)(sm + P_A16);
                            unsigned short* pw16 = (unsigned short*)(sm + P_W16);
#pragma unroll
                            for (int it = 0; it < 8; it++) {
                                int v = tid + NTHREADS * it;   // 0..1023
                                int row = v >> 3, seg = v & 7;
                                float4 f = *(const float4*)(pa + row * 36 + seg * 4);
                                __half2 h0 = __floats2half2_rn(f.x, f.y);
                                __half2 h1 = __floats2half2_rn(f.z, f.w);
                                uint2 o; o.x = *(unsigned*)&h0; o.y = *(unsigned*)&h1;
                                *(uint2*)(pa16 + row * 40 + seg * 4) = o;
                            }
#pragma unroll
                            for (int it = 0; it < 4; it++) {
                                int v = tid + NTHREADS * it;   // 0..511
                                int row = v >> 3, seg = v & 7;
                                float4 f = *(const float4*)(pw + row * 36 + seg * 4);
                                __half2 h0 = __floats2half2_rn(f.x, f.y);
                                __half2 h1 = __floats2half2_rn(f.z, f.w);
                                uint2 o; o.x = *(unsigned*)&h0; o.y = *(unsigned*)&h1;
                                *(uint2*)(pw16 + row * 40 + seg * 4) = o;
                            }
                        }
                        __syncthreads();
                        // fp16 mma over the 32-wide chunk (2 k16 steps)
                        {
                            const unsigned short* pa16 = (const unsigned short*)(sm + P_A16);
                            const unsigned short* pw16 = (const unsigned short*)(sm + P_W16);
#pragma unroll
                            for (int kk = 0; kk < 2; kk++) {
                                uint32_t ua[4][4];
#pragma unroll
                                for (int s = 0; s < 4; s++) {
                                    if (mh * 128 + wm * 64 + s * 16 < actp) {
                                        int base = (wm * 64 + s * 16 + g) * 40 + kk * 16 + 2 * tg;
                                        ua[s][0] = *(const unsigned*)(pa16 + base);
                                        ua[s][1] = *(const unsigned*)(pa16 + base + 8 * 40);
                                        ua[s][2] = *(const unsigned*)(pa16 + base + 8);
                                        ua[s][3] = *(const unsigned*)(pa16 + base + 8 * 40 + 8);
                                    }
                                }
#pragma unroll
                                for (int u = 0; u < 4; u++) {
                                    int wb = (wn * 32 + u * 8 + g) * 40 + kk * 16 + 2 * tg;
                                    uint32_t b0 = *(const unsigned*)(pw16 + wb);
                                    uint32_t b1 = *(const unsigned*)(pw16 + wb + 8);
#pragma unroll
                                    for (int s = 0; s < 4; s++)
                                        if (mh * 128 + wm * 64 + s * 16 < actp)
                                            mma16h(acc[s][u], ua[s][0], ua[s][1], ua[s][2], ua[s][3], b0, b1);
                                }
                            }
                        }
                        __syncthreads();
                    }
                    // store tile to g_xpart (quarter-interleaved storage rows)
#pragma unroll
                    for (int s = 0; s < 4; s++) {
                        int r0 = mh * 128 + wm * 64 + s * 16 + g;
                        if (mh * 128 + wm * 64 + s * 16 >= actp) continue;
#pragma unroll
                        for (int u = 0; u < 4; u++) {
                            int r1 = r0 + 8;
                            int c  = nt * 64 + wn * 32 + u * 8 + 2 * tg;
                            int ss0 = ((r0 & 3) << 6) | (r0 >> 2);
                            int ss1 = ((r1 & 3) << 6) | (r1 >> 2);
                            *(float2*)(g_xpart + ((size_t)t * BB + ss0) * HH + c) =
                                make_float2(acc[s][u][0], acc[s][u][1]);
                            *(float2*)(g_xpart + ((size_t)t * BB + ss1) * HH + c) =
                                make_float2(acc[s][u][2], acc[s][u][3]);
                        }
                    }
                }
            }
        }
    }

    if (!conv_first) convert_wh(Wh, bx, tid);

    gbar(2, NCTA);   // xpart + wh16 + h-init + flag reset globally visible

    // ============================================================
    // RECURRENT LOOP — per-quarter flag-synced, fp16, no per-step cvt
    // ============================================================
    {   // prefetch step-0 W16 + xpart + bias  [group G(0)]
        __half* ws = (__half*)(sm + L_W16);
#pragma unroll
        for (int it = 0; it < 16; it++) {
            int v = tid + NTHREADS * it; int row = v >> 5, seg = v & 31;
            cpa(ws + row * 264 + seg * 8,
                g_wh16 + ((size_t)0 * HH + nblk * 64 + row) * HH + ks * 256 + seg * 8);
        }
        float* xps = sm + L_XP;
#pragma unroll
        for (int it = 0; it < 2; it++) {
            int v = tid + NTHREADS * it; int row = v >> 2, seg = v & 3;
            cpa(xps + row * 16 + seg * 4,
                g_xpart + ((size_t)0 * BB + qq * 64 + row) * HH + lh * 16 + seg * 4);
        }
        if (tid < 4)
            cpa(sm + L_BI + tid * 4, bias + lh * 16 + tid * 4);
        CPCOMMIT();
    }

    for (int t = 0; t < hmax; t++) {
        int cur = t & 1;
        int nxt = cur ^ 1;
        int act      = s_act[t];
        int act_prev = (t == 0) ? 64 : s_act[t - 1];
        int actL = (act + 15) & ~15;

        CPWAIT(0);          // W16/xpart/bias for step t resident
        __syncthreads();
        const unsigned short* w16h = (const unsigned short*)(sm + L_W16);

        // wait until my h K-slice (cols [256ks,+256)) for step t is ready
        waitflag(&g_hflag[qq][ks], 16u * (unsigned)t);

        const __half* hbuf = g_h[cur];

        float acc[2][4][4];
#pragma unroll
        for (int s = 0; s < 2; s++)
#pragma unroll
            for (int u = 0; u < 4; u++)
#pragma unroll
                for (int q = 0; q < 4; q++) acc[s][u][q] = 0.f;

        {   // A stage 0 (64 rows x 128 halves)
            __half* pa = (__half*)(sm + L_A);
            int ko = ks * 256;
#pragma unroll
            for (int it = 0; it < 8; it++) {
                int v = tid + NTHREADS * it; int row = v >> 4, seg = v & 15;
                if (row < actL)
                    cpa(pa + row * 136 + seg * 8,
                        hbuf + (size_t)(qq * 64 + row) * HH + ko + seg * 8);
            }
            CPCOMMIT();
        }
        for (int j = 0; j < 2; j++) {
            if (j == 0) {
                __half* pa1 = (__half*)(sm + L_A + L_A_BUF);
                int ko = ks * 256 + 128;
#pragma unroll
                for (int it = 0; it < 8; it++) {
                    int v = tid + NTHREADS * it; int row = v >> 4, seg = v & 15;
                    if (row < actL)
                        cpa(pa1 + row * 136 + seg * 8,
                            hbuf + (size_t)(qq * 64 + row) * HH + ko + seg * 8);
                }
                CPCOMMIT();
                CPWAIT(1);
            } else {
                CPWAIT(0);
            }
            __syncthreads();
            const unsigned short* pa = (const unsigned short*)(sm + L_A + j * L_A_BUF);
#pragma unroll
            for (int kk = 0; kk < 8; kk++) {
                uint32_t ua[2][4];
#pragma unroll
                for (int s = 0; s < 2; s++) {
                    if (wm * 32 + s * 16 < act) {
                        int base = (wm * 32 + s * 16 + g) * 136 + kk * 16 + 2 * tg;
                        ua[s][0] = *(const unsigned*)(pa + base);
                        ua[s][1] = *(const unsigned*)(pa + base + 8 * 136);
                        ua[s][2] = *(const unsigned*)(pa + base + 8);
                        ua[s][3] = *(const unsigned*)(pa + base + 8 * 136 + 8);
                    }
                }
#pragma unroll
                for (int u = 0; u < 4; u++) {
                    int wb = (wn * 32 + u * 8 + g) * 264 + j * 128 + kk * 16 + 2 * tg;
                    uint32_t b0 = *(const unsigned*)(w16h + wb);
                    uint32_t b1 = *(const unsigned*)(w16h + wb + 8);
#pragma unroll
                    for (int s = 0; s < 2; s++)
                        if (wm * 32 + s * 16 < act)
                            mma16h(acc[s][u], ua[s][0], ua[s][1], ua[s][2], ua[s][3], b0, b1);
                }
            }
            __syncthreads();
        }

        {   // prefetch next step's W16 + xpart + bias  [group G(t+1)]
            int tn = (t + 1 < TT) ? (t + 1) : (TT - 1);
            __half* wsn = (__half*)(sm + L_W16);
#pragma unroll
            for (int it = 0; it < 16; it++) {
                int v = tid + NTHREADS * it; int row = v >> 5, seg = v & 31;
                cpa(wsn + row * 264 + seg * 8,
                    g_wh16 + ((size_t)tn * HH + nblk * 64 + row) * HH + ks * 256 + seg * 8);
            }
            float* xps = sm + L_XP + nxt * L_XP_BUF;
#pragma unroll
            for (int it = 0; it < 2; it++) {
                int v = tid + NTHREADS * it; int row = v >> 2, seg = v & 3;
                cpa(xps + row * 16 + seg * 4,
                    g_xpart + ((size_t)tn * BB + qq * 64 + row) * HH + lh * 16 + seg * 4);
            }
            if (tid < 4)
                cpa(sm + L_BI + nxt * L_BI_BUF + tid * 4,
                    bias + (size_t)tn * HH + lh * 16 + tid * 4);
            CPCOMMIT();
        }

        {   // store split-K partial (fp32, active rows)
            float* P = g_part[cur] + (size_t)(qq * 64 + lh) * 4096;
#pragma unroll
            for (int s = 0; s < 2; s++) {
                if (wm * 32 + s * 16 >= act) continue;
#pragma unroll
                for (int u = 0; u < 4; u++) {
                    int r = wm * 32 + s * 16 + g;
                    int c = wn * 32 + u * 8 + 2 * tg;
                    *(float2*)&P[r * 64 + c]       = make_float2(acc[s][u][0], acc[s][u][1]);
                    *(float2*)&P[(r + 8) * 64 + c] = make_float2(acc[s][u][2], acc[s][u][3]);
                }
            }
        }
        arrive(&g_pflag[qq][nblk]);

        // wait for the 4 producers of MY col range (nblk = lh>>2)
        waitflag(&g_pflag[qq][lh >> 2], 4u * (unsigned)(t + 1));

        {   // reduce 4 partials + xpart + bias -> tanh -> fp16 -> h[nxt]
            int r = tid >> 1;            // 0..63
            int c8  = (tid & 1) * 8;
            int cg_ = lh * 16 + c8;
            if (r < act) {
                int nb4 = (cg_ >> 6) * 4;
                int cl0 = cg_ & 63;
                float v[8];
#pragma unroll
                for (int q = 0; q < 8; q++) v[q] = 0.f;
#pragma unroll
                for (int ksp = 0; ksp < 4; ksp++) {
                    const float4* p = (const float4*)&g_part[cur][
                        (size_t)(qq * 64 + nb4 + ksp) * 4096 + r * 64 + cl0];
                    float4 a = __ldcg(p);
                    float4 b = __ldcg(p + 1);
                    v[0] += a.x; v[1] += a.y; v[2] += a.z; v[3] += a.w;
                    v[4] += b.x; v[5] += b.y; v[6] += b.z; v[7] += b.w;
                }
                const float* xps = sm + L_XP + cur * L_XP_BUF + r * 16 + c8;
                const float* bs  = sm + L_BI + cur * L_BI_BUF + c8;
#pragma unroll
                for (int q = 0; q < 8; q++)
                    v[q] = tanhf(v[q] + xps[q] + bs[q]);

                __half2 p0 = __floats2half2_rn(v[0], v[1]);
                __half2 p1 = __floats2half2_rn(v[2], v[3]);
                __half2 p2 = __floats2half2_rn(v[4], v[5]);
                __half2 p3 = __floats2half2_rn(v[6], v[7]);
                uint4 o;
                o.x = *(unsigned*)&p0; o.y = *(unsigned*)&p1;
                o.z = *(unsigned*)&p2; o.w = *(unsigned*)&p3;
                *(uint4*)(&g_h[nxt][(size_t)(qq * 64 + r) * HH + cg_]) = o;
            } else if (r < act_prev) {
                const uint4* src = (const uint4*)(&g_h[cur][(size_t)(qq * 64 + r) * HH + cg_]);
                uint4* dst = (uint4*)(&g_h[nxt][(size_t)(qq * 64 + r) * HH + cg_]);
                dst[0] = __ldcg(src);
            }
        }
        arrive(&g_hflag[qq][lh >> 4]);
    }

    CPWAIT(0);
    gbar(2, NCTA);   // all h writes globally visible

    // ---- output: CTA bx handles storage row bx ----
    {
        int sr = bx;
        int rank = 4 * (sr & 63) + (sr >> 6);
        int ob = s_perm[rank];
        const __half* hfin = g_h[hmax & 1];   // parity of OWN quarter's loop
        float* red = sm;
        float p = 0.f;
        for (int c2 = tid * 2; c2 < HH; c2 += NTHREADS * 2) {
            unsigned uv = __ldcg((const unsigned*)(hfin + (size_t)sr * HH + c2));
            __half2 hv = *reinterpret_cast<__half2*>(&uv);
            p += __low2float(hv)  * __ldg(&Wout[c2]);
            p += __high2float(hv) * __ldg(&Wout[c2 + 1]);
        }
        red[tid] = p;
        __syncthreads();
        for (int s = 64; s > 0; s >>= 1) {
            if (tid < s) red[tid] += red[tid + s];
            __syncthreads();
        }
        if (tid == 0) out[ob] = red[0] + __ldg(&bout[0]);
    }
}

extern "C" void kernel_launch(void* const* d_in, const int* in_sizes, int n_in,
                              void* d_out, int out_size) {
    (void)in_sizes; (void)n_in; (void)out_size;
    const float* inp  = (const float*)d_in[0];
    const void*  slen = (const void*)d_in[1];
    const float* Wx   = (const float*)d_in[2];
    const float* Wh   = (const float*)d_in[3];
    const float* bias = (const float*)d_in[4];
    const float* Wout = (const float*)d_in[5];
    const float* bout = (const float*)d_in[6];
    float*       out  = (float*)d_out;

    static int s_attr_done = 0;
    if (!s_attr_done) {
        cudaFuncSetAttribute(SequenceModelPadded_kernel,
                             cudaFuncAttributeMaxDynamicSharedMemorySize, SMEM_BYTES);
        s_attr_done = 1;
    }
    SequenceModelPadded_kernel<<<NCTA, NTHREADS, SMEM_BYTES>>>(
        inp, slen, Wx, Wh, bias, Wout, bout, out);
}

// round 15
// speedup vs baseline: 1.0296x; 1.0296x over previous
#include <cuda_runtime.h>
#include <cuda_fp16.h>
#include <cstdint>
#include <cstddef>

#define BB 256
#define TT 256
#define II 512
#define HH 1024

#define NTHREADS 256
#define NCTA 128
#define HALFC 64

// ---- loop-phase dynamic smem layout (float offsets) ----
#define L_A       0
#define L_A_BUF   8704                // A stage: 128 rows x 136 halves
#define L_W16     17408               // W fp16: 2 x (64 x 264 halves = 8448 floats)
#define L_W16_BUF 8448
#define L_XP      (L_W16 + 2*L_W16_BUF)   // 34304
#define L_XP_BUF  (128*16)
#define L_BI      (L_XP + 2*L_XP_BUF)     // 38400
#define L_BI_BUF  16
#define SMEM_FLOATS (L_BI + 2*L_BI_BUF)   // 38432
#define SMEM_BYTES  (SMEM_FLOATS*4)       // 153728 B

// ---- prologue-phase aliased smem layout (temporally disjoint) ----
#define P_A32    0
#define P_A32_BUF (256*36)            // 9216
#define P_W32    (2*P_A32_BUF)        // 18432
#define P_W32_BUF (128*36)            // 4608 -> ends 27648
#define P_A16    27648                // 256 x 40 halves = 5120 floats
#define P_W16    (P_A16 + 5120)       // 32768: 128 x 40 halves = 2560 floats -> ends 35328

// ---- persistent device state ----
__device__ __half   g_h[2][BB * HH];                 // double-buffered h (fp16)
__device__ __half   g_wh16[(size_t)TT * HH * HH];    // Wh pre-converted to fp16 (512MB)
__device__ float    g_part[2][2 * 64 * 8192];        // [parity][(half*64+lh)*8192] fp32
__device__ float    g_xpart[(size_t)TT * BB * HH];   // x@Wx^T fp32, sorted rows
__device__ unsigned g_cnt[3];
__device__ unsigned g_gen[3];
__device__ unsigned g_pflag[2][16];                  // partial producers per nblk
__device__ unsigned g_hflag[2][4];                   // h writers per ks-group

// ---- grid barrier ----
__device__ __forceinline__ void gbar(int idx, unsigned count) {
    __threadfence();
    __syncthreads();
    if (threadIdx.x == 0) {
        volatile unsigned* vg = (volatile unsigned*)&g_gen[idx];
        unsigned g = *vg;
        unsigned old = atomicAdd(&g_cnt[idx], 1u);
        if (old == count - 1) {
            g_cnt[idx] = 0;
            __threadfence();
            *vg = g + 1;
        } else {
            while (*vg == g) {}
            __threadfence();
        }
    }
    __syncthreads();
}

// ---- monotonic flag sync ----
__device__ __forceinline__ void arrive(unsigned* f) {
    __threadfence();
    __syncthreads();
    if (threadIdx.x == 0) atomicAdd(f, 1u);
}
__device__ __forceinline__ void waitflag(unsigned* f, unsigned target) {
    __syncthreads();
    if (threadIdx.x == 0) {
        volatile unsigned* vf = (volatile unsigned*)f;
        while (*vf < target) {}
        __threadfence();
    }
    __syncthreads();
}

// ---- helpers ----
__device__ __forceinline__ void cpa(void* dst, const void* src) {
    uint32_t d = (uint32_t)__cvta_generic_to_shared(dst);
    asm volatile("cp.async.cg.shared.global [%0], [%1], 16;" :: "r"(d), "l"(src));
}
#define CPCOMMIT() asm volatile("cp.async.commit_group;")
#define CPWAIT(n)  asm volatile("cp.async.wait_group %0;" :: "n"(n))

// fp16 mma: m16n8k16, fp32 accum
__device__ __forceinline__ void mma16h(float* c, uint32_t a0, uint32_t a1,
                                       uint32_t a2, uint32_t a3,
                                       uint32_t b0, uint32_t b1) {
    asm volatile(
        "mma.sync.aligned.m16n8k16.row.col.f32.f16.f16.f32 "
        "{%0,%1,%2,%3},{%4,%5,%6,%7},{%8,%9},{%0,%1,%2,%3};"
        : "+f"(c[0]), "+f"(c[1]), "+f"(c[2]), "+f"(c[3])
        : "r"(a0), "r"(a1), "r"(a2), "r"(a3), "r"(b0), "r"(b1));
}

// convert Wh[t] (1M fp32) -> g_wh16[t]
__device__ __forceinline__ void convert_wh(const float* __restrict__ Wh, int t, int tid) {
    const float4* src = (const float4*)(Wh + (size_t)t * HH * HH);
    unsigned short* dst = (unsigned short*)(g_wh16 + (size_t)t * HH * HH);
    for (int i = tid; i < (HH * HH) / 4; i += NTHREADS) {
        float4 f = __ldcg(&src[i]);
        __half2 h0 = __floats2half2_rn(f.x, f.y);
        __half2 h1 = __floats2half2_rn(f.z, f.w);
        uint2 o;
        o.x = *(unsigned*)&h0;
        o.y = *(unsigned*)&h1;
        *(uint2*)(dst + i * 4) = o;
    }
}

// ---- persistent kernel ----
__global__ void __launch_bounds__(NTHREADS, 1)
SequenceModelPadded_kernel(
    const float* __restrict__ inp,        // (B,T,I)
    const void*  __restrict__ slen_raw,   // (B,) int64 OR int32
    const float* __restrict__ Wx,         // (T,H,I)
    const float* __restrict__ Wh,         // (T,H,H)
    const float* __restrict__ bias,       // (T,H)
    const float* __restrict__ Wout,       // (1,H)
    const float* __restrict__ bout,       // (1,)
    float* __restrict__ out)              // (B,1)
{
    extern __shared__ float sm[];
    __shared__ int s_is64;
    __shared__ int s_perm[256];
    __shared__ int s_lorig[256];
    __shared__ int s_lsorted[256];
    __shared__ int s_act[256];

    int tid  = threadIdx.x;
    int bx   = blockIdx.x;
    int half = bx >> 6;
    int lh   = bx & 63;
    int nblk = lh >> 2;          // 0..15 (N tile of 64 cols)
    int ks   = lh & 3;           // 0..3  (K split of 256)

    int lane = tid & 31, warp = tid >> 5;
    int wm = warp & 3, wn = warp >> 2;   // 4 x 2 warp grid
    int g  = lane >> 2, tg = lane & 3;

    // ---- seq_lengths dtype sniff ----
    if (tid == 0) {
        const unsigned* w = (const unsigned*)slen_raw;
        unsigned z = 0;
        for (int i = 1; i < 256; i += 2) z |= __ldg(&w[i]);
        s_is64 = (z == 0) ? 1 : 0;
    }
    __syncthreads();
    const int is64 = s_is64;

    // ---- stable sort of lengths (descending) ----
    {
        int L = is64 ? (int)__ldg(&((const int*)slen_raw)[tid * 2])
                     : (int)__ldg(&((const int*)slen_raw)[tid]);
        s_lorig[tid] = L;
        __syncthreads();
        int rank = 0;
        for (int j = 0; j < 256; j++) {
            int Lj = s_lorig[j];
            rank += (Lj > L) || (Lj == L && j < tid);
        }
        s_perm[rank]    = tid;
        s_lsorted[rank] = L;
        __syncthreads();
        int a = 0;
        for (int rl = 0; rl < 128; rl++)
            a += (s_lsorted[2 * rl + half] > tid) ? 1 : 0;
        s_act[tid] = a;
        __syncthreads();
    }
    const int hmax = s_lsorted[half];

    // ---- zero BOTH h buffers ----
    for (int e = tid; e < 1024; e += NTHREADS) {
        ((unsigned*)&g_h[0][0])[bx * 1024 + e] = 0u;
        ((unsigned*)&g_h[1][0])[bx * 1024 + e] = 0u;
    }

    // ---- reset flags ----
    if (bx == 0 && tid == 0) {
        for (int i = 0; i < 16; i++) { g_pflag[0][i] = 0; g_pflag[1][i] = 0; }
        for (int i = 0; i < 4;  i++) { g_hflag[0][i] = 0; g_hflag[1][i] = 0; }
    }

    // ============================================================
    // PROLOGUE 1 (fp16 mma): xpart[t, ss(r)] = x[perm[r],t] @ Wx[t]^T
    // ============================================================
    for (int rep = 0; rep < 2; rep++) {
        int t = bx + rep * 128;
        int actp = 0;
        for (int j = 0; j < 256; j++) actp += (s_lsorted[j] > t) ? 1 : 0;
        if (actp == 0) continue;
        int actpL = (actp + 15) & ~15;

        for (int nt = 0; nt < 8; nt++) {
            float acc[4][8][4];
#pragma unroll
            for (int s = 0; s < 4; s++)
#pragma unroll
                for (int u = 0; u < 8; u++)
#pragma unroll
                    for (int q = 0; q < 4; q++) acc[s][u][q] = 0.f;

            {   // chunk 0 fp32 loads
                float* pa = sm + P_A32;
                float* pw = sm + P_W32;
#pragma unroll
                for (int it = 0; it < 8; it++) {
                    int v = tid + NTHREADS * it; int row = v >> 3, seg = v & 7;
                    if (row < actpL) {
                        int pr = s_perm[row];
                        cpa(pa + row * 36 + seg * 4,
                            inp + (size_t)pr * (TT * II) + (size_t)t * II + seg * 4);
                    }
                }
#pragma unroll
                for (int it = 0; it < 4; it++) {
                    int v = tid + NTHREADS * it; int row = v >> 3, seg = v & 7;
                    cpa(pw + row * 36 + seg * 4,
                        Wx + ((size_t)t * HH + nt * 128 + row) * II + seg * 4);
                }
                CPCOMMIT();
            }
            for (int ch = 0; ch < 16; ch++) {
                if (ch < 15) {
                    int nb = (ch + 1) & 1;
                    float* pa = sm + P_A32 + nb * P_A32_BUF;
                    float* pw = sm + P_W32 + nb * P_W32_BUF;
                    int ko = (ch + 1) * 32;
#pragma unroll
                    for (int it = 0; it < 8; it++) {
                        int v = tid + NTHREADS * it; int row = v >> 3, seg = v & 7;
                        if (row < actpL) {
                            int pr = s_perm[row];
                            cpa(pa + row * 36 + seg * 4,
                                inp + (size_t)pr * (TT * II) + (size_t)t * II + ko + seg * 4);
                        }
                    }
#pragma unroll
                    for (int it = 0; it < 4; it++) {
                        int v = tid + NTHREADS * it; int row = v >> 3, seg = v & 7;
                        cpa(pw + row * 36 + seg * 4,
                            Wx + ((size_t)t * HH + nt * 128 + row) * II + ko + seg * 4);
                    }
                    CPCOMMIT();
                    CPWAIT(1);
                } else {
                    CPWAIT(0);
                }
                __syncthreads();

                // cvt fp32 chunk -> fp16 tiles (once per element)
                {
                    const float* pa = sm + P_A32 + (ch & 1) * P_A32_BUF;
                    const float* pw = sm + P_W32 + (ch & 1) * P_W32_BUF;
                    unsigned short* pa16 = (unsigned short*)(sm + P_A16);
                    unsigned short* pw16 = (unsigned short*)(sm + P_W16);
#pragma unroll
                    for (int it = 0; it < 8; it++) {
                        int v = tid + NTHREADS * it;
                        int row = v >> 3, seg = v & 7;
                        float4 f = *(const float4*)(pa + row * 36 + seg * 4);
                        __half2 h0 = __floats2half2_rn(f.x, f.y);
                        __half2 h1 = __floats2half2_rn(f.z, f.w);
                        uint2 o; o.x = *(unsigned*)&h0; o.y = *(unsigned*)&h1;
                        *(uint2*)(pa16 + row * 40 + seg * 4) = o;
                    }
#pragma unroll
                    for (int it = 0; it < 4; it++) {
                        int v = tid + NTHREADS * it;
                        int row = v >> 3, seg = v & 7;
                        float4 f = *(const float4*)(pw + row * 36 + seg * 4);
                        __half2 h0 = __floats2half2_rn(f.x, f.y);
                        __half2 h1 = __floats2half2_rn(f.z, f.w);
                        uint2 o; o.x = *(unsigned*)&h0; o.y = *(unsigned*)&h1;
                        *(uint2*)(pw16 + row * 40 + seg * 4) = o;
                    }
                }
                __syncthreads();

                // fp16 mma over the 32-wide chunk (2 k16 steps)
                {
                    const unsigned short* pa16 = (const unsigned short*)(sm + P_A16);
                    const unsigned short* pw16 = (const unsigned short*)(sm + P_W16);
#pragma unroll
                    for (int kk = 0; kk < 2; kk++) {
                        uint32_t ua[4][4];
#pragma unroll
                        for (int s = 0; s < 4; s++) {
                            if (wm * 64 + s * 16 < actp) {
                                int base = (wm * 64 + s * 16 + g) * 40 + kk * 16 + 2 * tg;
                                ua[s][0] = *(const unsigned*)(pa16 + base);
                                ua[s][1] = *(const unsigned*)(pa16 + base + 8 * 40);
                                ua[s][2] = *(const unsigned*)(pa16 + base + 8);
                                ua[s][3] = *(const unsigned*)(pa16 + base + 8 * 40 + 8);
                            }
                        }
#pragma unroll
                        for (int u = 0; u < 8; u++) {
                            int wb = (wn * 64 + u * 8 + g) * 40 + kk * 16 + 2 * tg;
                            uint32_t b0 = *(const unsigned*)(pw16 + wb);
                            uint32_t b1 = *(const unsigned*)(pw16 + wb + 8);
#pragma unroll
                            for (int s = 0; s < 4; s++)
                                if (wm * 64 + s * 16 < actp)
                                    mma16h(acc[s][u], ua[s][0], ua[s][1], ua[s][2], ua[s][3], b0, b1);
                        }
                    }
                }
                __syncthreads();
            }
#pragma unroll
            for (int s = 0; s < 4; s++) {
                if (wm * 64 + s * 16 >= actp) continue;
#pragma unroll
                for (int u = 0; u < 8; u++) {
                    int r0 = wm * 64 + s * 16 + g;
                    int r1 = r0 + 8;
                    int c  = nt * 128 + wn * 64 + u * 8 + 2 * tg;
                    int ss0 = ((r0 & 1) << 7) | (r0 >> 1);
                    int ss1 = ((r1 & 1) << 7) | (r1 >> 1);
                    *(float2*)(g_xpart + ((size_t)t * BB + ss0) * HH + c) =
                        make_float2(acc[s][u][0], acc[s][u][1]);
                    *(float2*)(g_xpart + ((size_t)t * BB + ss1) * HH + c) =
                        make_float2(acc[s][u][2], acc[s][u][3]);
                }
            }
        }
    }

    // ============================================================
    // PROLOGUE 2: Wh -> fp16 (each CTA converts t = bx and bx+128)
    // ============================================================
    convert_wh(Wh, bx, tid);
    convert_wh(Wh, bx + 128, tid);

    gbar(2, NCTA);   // xpart + wh16 + h-init + flag reset globally visible

    // ============================================================
    // RECURRENT LOOP — R13 structure, fp16 W direct (no per-step cvt)
    // ============================================================
    {   // prefetch step-0 W16 + xpart + bias into buffer 0
        __half* ws = (__half*)(sm + L_W16);
#pragma unroll
        for (int it = 0; it < 8; it++) {
            int v = tid + NTHREADS * it; int row = v >> 5, seg = v & 31;
            cpa(ws + row * 264 + seg * 8,
                g_wh16 + ((size_t)nblk * 64 + row) * HH + ks * 256 + seg * 8);
        }
        float* xps = sm + L_XP;
#pragma unroll
        for (int it = 0; it < 2; it++) {
            int v = tid + NTHREADS * it; int row = v >> 2, seg = v & 3;
            cpa(xps + row * 16 + seg * 4,
                g_xpart + ((size_t)half * 128 + row) * HH + lh * 16 + seg * 4);
        }
        if (tid < 4)
            cpa(sm + L_BI + tid * 4, bias + lh * 16 + tid * 4);
        CPCOMMIT();
    }

    for (int t = 0; t < hmax; t++) {
        int cur = t & 1;
        int nxt = cur ^ 1;
        int act      = s_act[t];
        int act_prev = (t == 0) ? 128 : s_act[t - 1];
        int actL = (act + 15) & ~15;

        CPWAIT(0);          // W16/xpart/bias group for step t resident
        __syncthreads();
        const unsigned short* w16h =
            (const unsigned short*)(sm + L_W16 + cur * L_W16_BUF);

        // wait until my h K-slice (cols [256ks,+256)) for step t is ready
        waitflag(&g_hflag[half][ks], 16u * (unsigned)t);

        const __half* hbuf = g_h[cur];

        float acc[2][4][4];
#pragma unroll
        for (int s = 0; s < 2; s++)
#pragma unroll
            for (int u = 0; u < 4; u++)
#pragma unroll
                for (int q = 0; q < 4; q++) acc[s][u][q] = 0.f;

        {   // A stage 0 (128 halves wide)
            __half* pa = (__half*)(sm + L_A);
            int ko = ks * 256;
#pragma unroll
            for (int it = 0; it < 8; it++) {
                int v = tid + NTHREADS * it; int row = v >> 4, seg = v & 15;
                if (row < actL)
                    cpa(pa + row * 136 + seg * 8,
                        hbuf + (size_t)(half * 128 + row) * HH + ko + seg * 8);
            }
            CPCOMMIT();
        }
        for (int j = 0; j < 2; j++) {
            if (j == 0) {
                __half* pa1 = (__half*)(sm + L_A + L_A_BUF);
                int ko = ks * 256 + 128;
#pragma unroll
                for (int it = 0; it < 8; it++) {
                    int v = tid + NTHREADS * it; int row = v >> 4, seg = v & 15;
                    if (row < actL)
                        cpa(pa1 + row * 136 + seg * 8,
                            hbuf + (size_t)(half * 128 + row) * HH + ko + seg * 8);
                }
                CPCOMMIT();
                CPWAIT(1);
            } else {
                CPWAIT(0);
            }
            __syncthreads();
            const unsigned short* pa = (const unsigned short*)(sm + L_A + j * L_A_BUF);
#pragma unroll
            for (int kk = 0; kk < 8; kk++) {
                uint32_t ua[2][4];
#pragma unroll
                for (int s = 0; s < 2; s++) {
                    if (wm * 32 + s * 16 < act) {
                        int base = (wm * 32 + s * 16 + g) * 136 + kk * 16 + 2 * tg;
                        ua[s][0] = *(const unsigned*)(pa + base);
                        ua[s][1] = *(const unsigned*)(pa + base + 8 * 136);
                        ua[s][2] = *(const unsigned*)(pa + base + 8);
                        ua[s][3] = *(const unsigned*)(pa + base + 8 * 136 + 8);
                    }
                }
#pragma unroll
                for (int u = 0; u < 4; u++) {
                    int wb = (wn * 32 + u * 8 + g) * 264 + j * 128 + kk * 16 + 2 * tg;
                    uint32_t b0 = *(const unsigned*)(w16h + wb);
                    uint32_t b1 = *(const unsigned*)(w16h + wb + 8);
#pragma unroll
                    for (int s = 0; s < 2; s++)
                        if (wm * 32 + s * 16 < act)
                            mma16h(acc[s][u], ua[s][0], ua[s][1], ua[s][2], ua[s][3], b0, b1);
                }
            }
            __syncthreads();
        }

        {   // prefetch next step's W16 + xpart + bias
            int tn = (t + 1 < TT) ? (t + 1) : (TT - 1);
            __half* wsn = (__half*)(sm + L_W16 + nxt * L_W16_BUF);
#pragma unroll
            for (int it = 0; it < 8; it++) {
                int v = tid + NTHREADS * it; int row = v >> 5, seg = v & 31;
                cpa(wsn + row * 264 + seg * 8,
                    g_wh16 + ((size_t)tn * HH + nblk * 64 + row) * HH + ks * 256 + seg * 8);
            }
            float* xps = sm + L_XP + nxt * L_XP_BUF;
#pragma unroll
            for (int it = 0; it < 2; it++) {
                int v = tid + NTHREADS * it; int row = v >> 2, seg = v & 3;
                cpa(xps + row * 16 + seg * 4,
                    g_xpart + ((size_t)tn * BB + half * 128 + row) * HH + lh * 16 + seg * 4);
            }
            if (tid < 4)
                cpa(sm + L_BI + nxt * L_BI_BUF + tid * 4,
                    bias + (size_t)tn * HH + lh * 16 + tid * 4);
            CPCOMMIT();
        }

        {   // store split-K partial (fp32, active rows) into parity buffer
            float* P = g_part[cur] + (size_t)(half * 64 + lh) * 8192;
#pragma unroll
            for (int s = 0; s < 2; s++) {
                if (wm * 32 + s * 16 >= act) continue;
#pragma unroll
                for (int u = 0; u < 4; u++) {
                    int r = wm * 32 + s * 16 + g;
                    int c = wn * 32 + u * 8 + 2 * tg;
                    *(float2*)&P[r * 64 + c]       = make_float2(acc[s][u][0], acc[s][u][1]);
                    *(float2*)&P[(r + 8) * 64 + c] = make_float2(acc[s][u][2], acc[s][u][3]);
                }
            }
        }
        arrive(&g_pflag[half][nblk]);

        // wait for the 4 producers of MY col range (nblk = lh>>2)
        waitflag(&g_pflag[half][lh >> 2], 4u * (unsigned)(t + 1));

        {   // reduce 4 partials + xpart + bias -> tanh -> fp16 -> h[nxt]
            int r = tid >> 1;
            int c8  = (tid & 1) * 8;
            int cg_ = lh * 16 + c8;
            if (r < act) {
                int nb4 = (cg_ >> 6) * 4;
                int cl0 = cg_ & 63;
                float v[8];
#pragma unroll
                for (int q = 0; q < 8; q++) v[q] = 0.f;
#pragma unroll
                for (int ksp = 0; ksp < 4; ksp++) {
                    const float4* p = (const float4*)&g_part[cur][
                        (size_t)(half * 64 + nb4 + ksp) * 8192 + r * 64 + cl0];
                    float4 a = __ldcg(p);
                    float4 b = __ldcg(p + 1);
                    v[0] += a.x; v[1] += a.y; v[2] += a.z; v[3] += a.w;
                    v[4] += b.x; v[5] += b.y; v[6] += b.z; v[7] += b.w;
                }
                const float* xps = sm + L_XP + cur * L_XP_BUF + r * 16 + c8;
                const float* bs  = sm + L_BI + cur * L_BI_BUF + c8;
#pragma unroll
                for (int q = 0; q < 8; q++)
                    v[q] = tanhf(v[q] + xps[q] + bs[q]);

                __half2 p0 = __floats2half2_rn(v[0], v[1]);
                __half2 p1 = __floats2half2_rn(v[2], v[3]);
                __half2 p2 = __floats2half2_rn(v[4], v[5]);
                __half2 p3 = __floats2half2_rn(v[6], v[7]);
                uint4 o;
                o.x = *(unsigned*)&p0; o.y = *(unsigned*)&p1;
                o.z = *(unsigned*)&p2; o.w = *(unsigned*)&p3;
                *(uint4*)(&g_h[nxt][(size_t)(half * 128 + r) * HH + cg_]) = o;
            } else if (r < act_prev) {
                const uint4* src = (const uint4*)(&g_h[cur][(size_t)(half * 128 + r) * HH + cg_]);
                uint4* dst = (uint4*)(&g_h[nxt][(size_t)(half * 128 + r) * HH + cg_]);
                dst[0] = __ldcg(src);
            }
        }
        arrive(&g_hflag[half][lh >> 4]);
    }

    CPWAIT(0);
    gbar(half, HALFC);   // all h writes of this half visible

    // ---- output: out[perm[2*rl+half]] = h . Wout + bout ----
    const __half* hfin = g_h[hmax & 1];
    float* red = sm;
#pragma unroll
    for (int rr = 0; rr < 2; rr++) {
        int rl = lh * 2 + rr;
        int gr = half * 128 + rl;
        int ob = s_perm[2 * rl + half];
        float p = 0.f;
        for (int c2 = tid * 2; c2 < HH; c2 += NTHREADS * 2) {
            unsigned uv = __ldcg((const unsigned*)(hfin + (size_t)gr * HH + c2));
            __half2 hv = *reinterpret_cast<__half2*>(&uv);
            p += __low2float(hv)  * __ldg(&Wout[c2]);
            p += __high2float(hv) * __ldg(&Wout[c2 + 1]);
        }
        red[tid] = p;
        __syncthreads();
        for (int s = 128; s > 0; s >>= 1) {
            if (tid < s) red[tid] += red[tid + s];
            __syncthreads();
        }
        if (tid == 0) out[ob] = red[0] + __ldg(&bout[0]);
        __syncthreads();
    }
}

extern "C" void kernel_launch(void* const* d_in, const int* in_sizes, int n_in,
                              void* d_out, int out_size) {
    (void)in_sizes; (void)n_in; (void)out_size;
    const float* inp  = (const float*)d_in[0];
    const void*  slen = (const void*)d_in[1];
    const float* Wx   = (const float*)d_in[2];
    const float* Wh   = (const float*)d_in[3];
    const float* bias = (const float*)d_in[4];
    const float* Wout = (const float*)d_in[5];
    const float* bout = (const float*)d_in[6];
    float*       out  = (float*)d_out;

    static int s_attr_done = 0;
    if (!s_attr_done) {
        cudaFuncSetAttribute(SequenceModelPadded_kernel,
                             cudaFuncAttributeMaxDynamicSharedMemorySize, SMEM_BYTES);
        s_attr_done = 1;
    }
    SequenceModelPadded_kernel<<<NCTA, NTHREADS, SMEM_BYTES>>>(
        inp, slen, Wx, Wh, bias, Wout, bout, out);
}

// round 16
// speedup vs baseline: 1.6124x; 1.5661x over previous
#include <cuda_runtime.h>
#include <cuda_fp16.h>
#include <cstdint>
#include <cstddef>

#define BB 256
#define TT 256
#define II 512
#define HH 1024

#define NTHREADS 256
#define NCTA 128
#define HALFC 64

// ---- loop-phase dynamic smem layout (float offsets) ----
#define L_A      0
#define L_A_BUF  8704                 // A stage: 128 rows x 136 halves
#define L_WS     (2*L_A_BUF)          // 17408: W fp32 staging 64 x 260
#define L_W16    (L_WS + 16640)       // 34048: W fp16 64 x 264 halves
#define L_XP     (L_W16 + 8448)       // 42496
#define L_XP_BUF (128*16)
#define L_BI     (L_XP + 2*L_XP_BUF)  // 46592
#define L_BI_BUF 16
#define SMEM_FLOATS (L_BI + 2*L_BI_BUF)  // 46624
#define SMEM_BYTES  (SMEM_FLOATS*4)      // 186496 B

// ---- prologue-phase aliased smem layout (temporally disjoint) ----
#define P_A32    0
#define P_A32_BUF (256*36)            // 9216
#define P_W32    (2*P_A32_BUF)        // 18432
#define P_W32_BUF (128*36)            // 4608 -> ends 27648
#define P_A16    27648                // 256 x 40 halves = 5120 floats
#define P_W16    (P_A16 + 5120)       // 32768: 128 x 40 halves = 2560 floats

// ---- persistent device state ----
__device__ __half   g_h[2][BB * HH];                 // double-buffered h (fp16)
__device__ float    g_part[2][2 * 64 * 8192];        // [parity][(half*64+lh)*8192] fp32
__device__ float    g_xpart[(size_t)TT * BB * HH];   // x@Wx^T fp32, sorted rows
__device__ unsigned g_cnt[3];
__device__ unsigned g_gen[3];
__device__ unsigned g_pflag[2][16];                  // partial producers per nblk
__device__ unsigned g_hflag[2][4];                   // h writers per ks-group

// ---- grid barrier (2 uses: post-prologue, pre-epilogue) ----
__device__ __forceinline__ void gbar(int idx, unsigned count) {
    __threadfence();
    __syncthreads();
    if (threadIdx.x == 0) {
        volatile unsigned* vg = (volatile unsigned*)&g_gen[idx];
        unsigned g = *vg;
        unsigned old = atomicAdd(&g_cnt[idx], 1u);
        if (old == count - 1) {
            g_cnt[idx] = 0;
            __threadfence();
            *vg = g + 1;
        } else {
            while (*vg == g) {}
            __threadfence();
        }
    }
    __syncthreads();
}

// ---- monotonic flag sync: release/acquire atomics (no MEMBAR.ALL) ----
__device__ __forceinline__ void arrive(unsigned* f) {
    __syncthreads();   // all CTA writes happen-before thread 0's release
    if (threadIdx.x == 0)
        asm volatile("red.release.gpu.add.u32 [%0], 1;" :: "l"(f) : "memory");
}
__device__ __forceinline__ void waitflag(unsigned* f, unsigned target) {
    __syncthreads();
    if (threadIdx.x == 0) {
        unsigned v;
        do {
            asm volatile("ld.acquire.gpu.b32 %0, [%1];" : "=r"(v) : "l"(f) : "memory");
        } while (v < target);
    }
    __syncthreads();   // publish acquire to whole CTA
}

// ---- helpers ----
__device__ __forceinline__ void cpa(void* dst, const void* src) {
    uint32_t d = (uint32_t)__cvta_generic_to_shared(dst);
    asm volatile("cp.async.cg.shared.global [%0], [%1], 16;" :: "r"(d), "l"(src));
}
#define CPCOMMIT() asm volatile("cp.async.commit_group;")
#define CPWAIT(n)  asm volatile("cp.async.wait_group %0;" :: "n"(n))

// fp16 mma: m16n8k16, fp32 accum
__device__ __forceinline__ void mma16h(float* c, uint32_t a0, uint32_t a1,
                                       uint32_t a2, uint32_t a3,
                                       uint32_t b0, uint32_t b1) {
    asm volatile(
        "mma.sync.aligned.m16n8k16.row.col.f32.f16.f16.f32 "
        "{%0,%1,%2,%3},{%4,%5,%6,%7},{%8,%9},{%0,%1,%2,%3};"
        : "+f"(c[0]), "+f"(c[1]), "+f"(c[2]), "+f"(c[3])
        : "r"(a0), "r"(a1), "r"(a2), "r"(a3), "r"(b0), "r"(b1));
}

// ---- persistent kernel ----
__global__ void __launch_bounds__(NTHREADS, 1)
SequenceModelPadded_kernel(
    const float* __restrict__ inp,        // (B,T,I)
    const void*  __restrict__ slen_raw,   // (B,) int64 OR int32
    const float* __restrict__ Wx,         // (T,H,I)
    const float* __restrict__ Wh,         // (T,H,H)
    const float* __restrict__ bias,       // (T,H)
    const float* __restrict__ Wout,       // (1,H)
    const float* __restrict__ bout,       // (1,)
    float* __restrict__ out)              // (B,1)
{
    extern __shared__ float sm[];
    __shared__ int s_is64;
    __shared__ int s_perm[256];
    __shared__ int s_lorig[256];
    __shared__ int s_lsorted[256];
    __shared__ int s_act[256];

    int tid  = threadIdx.x;
    int bx   = blockIdx.x;
    int half = bx >> 6;
    int lh   = bx & 63;
    int nblk = lh >> 2;          // 0..15 (N tile of 64 cols)
    int ks   = lh & 3;           // 0..3  (K split of 256)

    int lane = tid & 31, warp = tid >> 5;
    int wm = warp & 3, wn = warp >> 2;   // 4 x 2 warp grid
    int g  = lane >> 2, tg = lane & 3;

    // ---- seq_lengths dtype sniff ----
    if (tid == 0) {
        const unsigned* w = (const unsigned*)slen_raw;
        unsigned z = 0;
        for (int i = 1; i < 256; i += 2) z |= __ldg(&w[i]);
        s_is64 = (z == 0) ? 1 : 0;
    }
    __syncthreads();
    const int is64 = s_is64;

    // ---- stable sort of lengths (descending) ----
    {
        int L = is64 ? (int)__ldg(&((const int*)slen_raw)[tid * 2])
                     : (int)__ldg(&((const int*)slen_raw)[tid]);
        s_lorig[tid] = L;
        __syncthreads();
        int rank = 0;
        for (int j = 0; j < 256; j++) {
            int Lj = s_lorig[j];
            rank += (Lj > L) || (Lj == L && j < tid);
        }
        s_perm[rank]    = tid;
        s_lsorted[rank] = L;
        __syncthreads();
        int a = 0;
        for (int rl = 0; rl < 128; rl++)
            a += (s_lsorted[2 * rl + half] > tid) ? 1 : 0;
        s_act[tid] = a;
        __syncthreads();
    }
    const int hmax = s_lsorted[half];

    // ---- zero BOTH h buffers ----
    for (int e = tid; e < 1024; e += NTHREADS) {
        ((unsigned*)&g_h[0][0])[bx * 1024 + e] = 0u;
        ((unsigned*)&g_h[1][0])[bx * 1024 + e] = 0u;
    }

    // ---- reset flags ----
    if (bx == 0 && tid == 0) {
        for (int i = 0; i < 16; i++) { g_pflag[0][i] = 0; g_pflag[1][i] = 0; }
        for (int i = 0; i < 4;  i++) { g_hflag[0][i] = 0; g_hflag[1][i] = 0; }
    }

    // ============================================================
    // PROLOGUE (fp16 mma): xpart[t, ss(r)] = x[perm[r],t] @ Wx[t]^T
    // ============================================================
    for (int rep = 0; rep < 2; rep++) {
        int t = bx + rep * 128;
        int actp = 0;
        for (int j = 0; j < 256; j++) actp += (s_lsorted[j] > t) ? 1 : 0;
        if (actp == 0) continue;
        int actpL = (actp + 15) & ~15;

        for (int nt = 0; nt < 8; nt++) {
            float acc[4][8][4];
#pragma unroll
            for (int s = 0; s < 4; s++)
#pragma unroll
                for (int u = 0; u < 8; u++)
#pragma unroll
                    for (int q = 0; q < 4; q++) acc[s][u][q] = 0.f;

            {   // chunk 0 fp32 loads
                float* pa = sm + P_A32;
                float* pw = sm + P_W32;
#pragma unroll
                for (int it = 0; it < 8; it++) {
                    int v = tid + NTHREADS * it; int row = v >> 3, seg = v & 7;
                    if (row < actpL) {
                        int pr = s_perm[row];
                        cpa(pa + row * 36 + seg * 4,
                            inp + (size_t)pr * (TT * II) + (size_t)t * II + seg * 4);
                    }
                }
#pragma unroll
                for (int it = 0; it < 4; it++) {
                    int v = tid + NTHREADS * it; int row = v >> 3, seg = v & 7;
                    cpa(pw + row * 36 + seg * 4,
                        Wx + ((size_t)t * HH + nt * 128 + row) * II + seg * 4);
                }
                CPCOMMIT();
            }
            for (int ch = 0; ch < 16; ch++) {
                if (ch < 15) {
                    int nb = (ch + 1) & 1;
                    float* pa = sm + P_A32 + nb * P_A32_BUF;
                    float* pw = sm + P_W32 + nb * P_W32_BUF;
                    int ko = (ch + 1) * 32;
#pragma unroll
                    for (int it = 0; it < 8; it++) {
                        int v = tid + NTHREADS * it; int row = v >> 3, seg = v & 7;
                        if (row < actpL) {
                            int pr = s_perm[row];
                            cpa(pa + row * 36 + seg * 4,
                                inp + (size_t)pr * (TT * II) + (size_t)t * II + ko + seg * 4);
                        }
                    }
#pragma unroll
                    for (int it = 0; it < 4; it++) {
                        int v = tid + NTHREADS * it; int row = v >> 3, seg = v & 7;
                        cpa(pw + row * 36 + seg * 4,
                            Wx + ((size_t)t * HH + nt * 128 + row) * II + ko + seg * 4);
                    }
                    CPCOMMIT();
                    CPWAIT(1);
                } else {
                    CPWAIT(0);
                }
                __syncthreads();

                // cvt fp32 chunk -> fp16 tiles (once per element)
                {
                    const float* pa = sm + P_A32 + (ch & 1) * P_A32_BUF;
                    const float* pw = sm + P_W32 + (ch & 1) * P_W32_BUF;
                    unsigned short* pa16 = (unsigned short*)(sm + P_A16);
                    unsigned short* pw16 = (unsigned short*)(sm + P_W16);
#pragma unroll
                    for (int it = 0; it < 8; it++) {
                        int v = tid + NTHREADS * it;
                        int row = v >> 3, seg = v & 7;
                        float4 f = *(const float4*)(pa + row * 36 + seg * 4);
                        __half2 h0 = __floats2half2_rn(f.x, f.y);
                        __half2 h1 = __floats2half2_rn(f.z, f.w);
                        uint2 o; o.x = *(unsigned*)&h0; o.y = *(unsigned*)&h1;
                        *(uint2*)(pa16 + row * 40 + seg * 4) = o;
                    }
#pragma unroll
                    for (int it = 0; it < 4; it++) {
                        int v = tid + NTHREADS * it;
                        int row = v >> 3, seg = v & 7;
                        float4 f = *(const float4*)(pw + row * 36 + seg * 4);
                        __half2 h0 = __floats2half2_rn(f.x, f.y);
                        __half2 h1 = __floats2half2_rn(f.z, f.w);
                        uint2 o; o.x = *(unsigned*)&h0; o.y = *(unsigned*)&h1;
                        *(uint2*)(pw16 + row * 40 + seg * 4) = o;
                    }
                }
                __syncthreads();

                // fp16 mma over the 32-wide chunk (2 k16 steps)
                {
                    const unsigned short* pa16 = (const unsigned short*)(sm + P_A16);
                    const unsigned short* pw16 = (const unsigned short*)(sm + P_W16);
#pragma unroll
                    for (int kk = 0; kk < 2; kk++) {
                        uint32_t ua[4][4];
#pragma unroll
                        for (int s = 0; s < 4; s++) {
                            if (wm * 64 + s * 16 < actp) {
                                int base = (wm * 64 + s * 16 + g) * 40 + kk * 16 + 2 * tg;
                                ua[s][0] = *(const unsigned*)(pa16 + base);
                                ua[s][1] = *(const unsigned*)(pa16 + base + 8 * 40);
                                ua[s][2] = *(const unsigned*)(pa16 + base + 8);
                                ua[s][3] = *(const unsigned*)(pa16 + base + 8 * 40 + 8);
                            }
                        }
#pragma unroll
                        for (int u = 0; u < 8; u++) {
                            int wb = (wn * 64 + u * 8 + g) * 40 + kk * 16 + 2 * tg;
                            uint32_t b0 = *(const unsigned*)(pw16 + wb);
                            uint32_t b1 = *(const unsigned*)(pw16 + wb + 8);
#pragma unroll
                            for (int s = 0; s < 4; s++)
                                if (wm * 64 + s * 16 < actp)
                                    mma16h(acc[s][u], ua[s][0], ua[s][1], ua[s][2], ua[s][3], b0, b1);
                        }
                    }
                }
                __syncthreads();
            }
#pragma unroll
            for (int s = 0; s < 4; s++) {
                if (wm * 64 + s * 16 >= actp) continue;
#pragma unroll
                for (int u = 0; u < 8; u++) {
                    int r0 = wm * 64 + s * 16 + g;
                    int r1 = r0 + 8;
                    int c  = nt * 128 + wn * 64 + u * 8 + 2 * tg;
                    int ss0 = ((r0 & 1) << 7) | (r0 >> 1);
                    int ss1 = ((r1 & 1) << 7) | (r1 >> 1);
                    *(float2*)(g_xpart + ((size_t)t * BB + ss0) * HH + c) =
                        make_float2(acc[s][u][0], acc[s][u][1]);
                    *(float2*)(g_xpart + ((size_t)t * BB + ss1) * HH + c) =
                        make_float2(acc[s][u][2], acc[s][u][3]);
                }
            }
        }
    }

    gbar(2, NCTA);   // xpart + h-init + flag reset globally visible

    // ============================================================
    // RECURRENT LOOP — R13 structure (fp16 GEMM, flag-synced)
    // ============================================================
    {   // prefetch step-0 W fp32 -> staging (single) + xpart + bias
        float* ws = sm + L_WS;
#pragma unroll
        for (int it = 0; it < 16; it++) {
            int v = tid + NTHREADS * it; int row = v >> 6, seg = v & 63;
            cpa(ws + row * 260 + seg * 4,
                Wh + ((size_t)nblk * 64 + row) * HH + ks * 256 + seg * 4);
        }
        float* xps = sm + L_XP;
#pragma unroll
        for (int it = 0; it < 2; it++) {
            int v = tid + NTHREADS * it; int row = v >> 2, seg = v & 3;
            cpa(xps + row * 16 + seg * 4,
                g_xpart + ((size_t)half * 128 + row) * HH + lh * 16 + seg * 4);
        }
        if (tid < 4)
            cpa(sm + L_BI + tid * 4, bias + lh * 16 + tid * 4);
        CPCOMMIT();
    }

    for (int t = 0; t < hmax; t++) {
        int cur = t & 1;
        int nxt = cur ^ 1;
        int act      = s_act[t];
        int act_prev = (t == 0) ? 128 : s_act[t - 1];
        int actL = (act + 15) & ~15;

        // drain prefetch; cvt W fp32 staging -> packed fp16 W16
        CPWAIT(0);
        __syncthreads();
        {
            const float* wst = sm + L_WS;
            unsigned* w16 = (unsigned*)(sm + L_W16);
#pragma unroll
            for (int it = 0; it < 16; it++) {
                int v = tid + NTHREADS * it;
                int row = v >> 6, q = v & 63;
                float4 f = *(const float4*)(wst + row * 260 + q * 4);
                __half2 h0 = __floats2half2_rn(f.x, f.y);
                __half2 h1 = __floats2half2_rn(f.z, f.w);
                uint2 o;
                o.x = *(unsigned*)&h0;
                o.y = *(unsigned*)&h1;
                *(uint2*)(w16 + row * 132 + q * 2) = o;
            }
        }
        __syncthreads();
        const unsigned short* w16h = (const unsigned short*)(sm + L_W16);

        // wait until my h K-slice (cols [256ks,+256)) for step t is ready
        waitflag(&g_hflag[half][ks], 16u * (unsigned)t);

        const __half* hbuf = g_h[cur];

        float acc[2][4][4];
#pragma unroll
        for (int s = 0; s < 2; s++)
#pragma unroll
            for (int u = 0; u < 4; u++)
#pragma unroll
                for (int q = 0; q < 4; q++) acc[s][u][q] = 0.f;

        {   // A stage 0 (128 halves wide)
            __half* pa = (__half*)(sm + L_A);
            int ko = ks * 256;
#pragma unroll
            for (int it = 0; it < 8; it++) {
                int v = tid + NTHREADS * it; int row = v >> 4, seg = v & 15;
                if (row < actL)
                    cpa(pa + row * 136 + seg * 8,
                        hbuf + (size_t)(half * 128 + row) * HH + ko + seg * 8);
            }
            CPCOMMIT();
        }
        for (int j = 0; j < 2; j++) {
            if (j == 0) {
                __half* pa1 = (__half*)(sm + L_A + L_A_BUF);
                int ko = ks * 256 + 128;
#pragma unroll
                for (int it = 0; it < 8; it++) {
                    int v = tid + NTHREADS * it; int row = v >> 4, seg = v & 15;
                    if (row < actL)
                        cpa(pa1 + row * 136 + seg * 8,
                            hbuf + (size_t)(half * 128 + row) * HH + ko + seg * 8);
                }
                CPCOMMIT();
                CPWAIT(1);
            } else {
                CPWAIT(0);
            }
            __syncthreads();
            const unsigned short* pa = (const unsigned short*)(sm + L_A + j * L_A_BUF);
#pragma unroll
            for (int kk = 0; kk < 8; kk++) {
                uint32_t ua[2][4];
#pragma unroll
                for (int s = 0; s < 2; s++) {
                    if (wm * 32 + s * 16 < act) {
                        int base = (wm * 32 + s * 16 + g) * 136 + kk * 16 + 2 * tg;
                        ua[s][0] = *(const unsigned*)(pa + base);
                        ua[s][1] = *(const unsigned*)(pa + base + 8 * 136);
                        ua[s][2] = *(const unsigned*)(pa + base + 8);
                        ua[s][3] = *(const unsigned*)(pa + base + 8 * 136 + 8);
                    }
                }
#pragma unroll
                for (int u = 0; u < 4; u++) {
                    int wb = (wn * 32 + u * 8 + g) * 264 + j * 128 + kk * 16 + 2 * tg;
                    uint32_t b0 = *(const unsigned*)(w16h + wb);
                    uint32_t b1 = *(const unsigned*)(w16h + wb + 8);
#pragma unroll
                    for (int s = 0; s < 2; s++)
                        if (wm * 32 + s * 16 < act)
                            mma16h(acc[s][u], ua[s][0], ua[s][1], ua[s][2], ua[s][3], b0, b1);
                }
            }
            __syncthreads();
        }

        {   // prefetch next step's W fp32 + xpart + bias
            int tn = (t + 1 < TT) ? (t + 1) : (TT - 1);
            float* wsn = sm + L_WS;
#pragma unroll
            for (int it = 0; it < 16; it++) {
                int v = tid + NTHREADS * it; int row = v >> 6, seg = v & 63;
                cpa(wsn + row * 260 + seg * 4,
                    Wh + ((size_t)tn * HH + nblk * 64 + row) * HH + ks * 256 + seg * 4);
            }
            float* xps = sm + L_XP + nxt * L_XP_BUF;
#pragma unroll
            for (int it = 0; it < 2; it++) {
                int v = tid + NTHREADS * it; int row = v >> 2, seg = v & 3;
                cpa(xps + row * 16 + seg * 4,
                    g_xpart + ((size_t)tn * BB + half * 128 + row) * HH + lh * 16 + seg * 4);
            }
            if (tid < 4)
                cpa(sm + L_BI + nxt * L_BI_BUF + tid * 4,
                    bias + (size_t)tn * HH + lh * 16 + tid * 4);
            CPCOMMIT();
        }

        {   // store split-K partial (fp32, active rows) into parity buffer
            float* P = g_part[cur] + (size_t)(half * 64 + lh) * 8192;
#pragma unroll
            for (int s = 0; s < 2; s++) {
                if (wm * 32 + s * 16 >= act) continue;
#pragma unroll
                for (int u = 0; u < 4; u++) {
                    int r = wm * 32 + s * 16 + g;
                    int c = wn * 32 + u * 8 + 2 * tg;
                    *(float2*)&P[r * 64 + c]       = make_float2(acc[s][u][0], acc[s][u][1]);
                    *(float2*)&P[(r + 8) * 64 + c] = make_float2(acc[s][u][2], acc[s][u][3]);
                }
            }
        }
        arrive(&g_pflag[half][nblk]);

        // wait for the 4 producers of MY col range (nblk = lh>>2)
        waitflag(&g_pflag[half][lh >> 2], 4u * (unsigned)(t + 1));

        {   // reduce 4 partials + xpart + bias -> tanh -> fp16 -> h[nxt]
            int r = tid >> 1;
            int c8  = (tid & 1) * 8;
            int cg_ = lh * 16 + c8;
            if (r < act) {
                int nb4 = (cg_ >> 6) * 4;
                int cl0 = cg_ & 63;
                float v[8];
#pragma unroll
                for (int q = 0; q < 8; q++) v[q] = 0.f;
#pragma unroll
                for (int ksp = 0; ksp < 4; ksp++) {
                    const float4* p = (const float4*)&g_part[cur][
                        (size_t)(half * 64 + nb4 + ksp) * 8192 + r * 64 + cl0];
                    float4 a = __ldcg(p);
                    float4 b = __ldcg(p + 1);
                    v[0] += a.x; v[1] += a.y; v[2] += a.z; v[3] += a.w;
                    v[4] += b.x; v[5] += b.y; v[6] += b.z; v[7] += b.w;
                }
                const float* xps = sm + L_XP + cur * L_XP_BUF + r * 16 + c8;
                const float* bs  = sm + L_BI + cur * L_BI_BUF + c8;
#pragma unroll
                for (int q = 0; q < 8; q++)
                    v[q] = tanhf(v[q] + xps[q] + bs[q]);

                __half2 p0 = __floats2half2_rn(v[0], v[1]);
                __half2 p1 = __floats2half2_rn(v[2], v[3]);
                __half2 p2 = __floats2half2_rn(v[4], v[5]);
                __half2 p3 = __floats2half2_rn(v[6], v[7]);
                uint4 o;
                o.x = *(unsigned*)&p0; o.y = *(unsigned*)&p1;
                o.z = *(unsigned*)&p2; o.w = *(unsigned*)&p3;
                *(uint4*)(&g_h[nxt][(size_t)(half * 128 + r) * HH + cg_]) = o;
            } else if (r < act_prev) {
                const uint4* src = (const uint4*)(&g_h[cur][(size_t)(half * 128 + r) * HH + cg_]);
                uint4* dst = (uint4*)(&g_h[nxt][(size_t)(half * 128 + r) * HH + cg_]);
                dst[0] = __ldcg(src);
            }
        }
        arrive(&g_hflag[half][lh >> 4]);
    }

    CPWAIT(0);
    gbar(half, HALFC);   // all h writes of this half visible

    // ---- output: out[perm[2*rl+half]] = h . Wout + bout ----
    const __half* hfin = g_h[hmax & 1];
    float* red = sm;
#pragma unroll
    for (int rr = 0; rr < 2; rr++) {
        int rl = lh * 2 + rr;
        int gr = half * 128 + rl;
        int ob = s_perm[2 * rl + half];
        float p = 0.f;
        for (int c2 = tid * 2; c2 < HH; c2 += NTHREADS * 2) {
            unsigned uv = __ldcg((const unsigned*)(hfin + (size_t)gr * HH + c2));
            __half2 hv = *reinterpret_cast<__half2*>(&uv);
            p += __low2float(hv)  * __ldg(&Wout[c2]);
            p += __high2float(hv) * __ldg(&Wout[c2 + 1]);
        }
        red[tid] = p;
        __syncthreads();
        for (int s = 128; s > 0; s >>= 1) {
            if (tid < s) red[tid] += red[tid + s];
            __syncthreads();
        }
        if (tid == 0) out[ob] = red[0] + __ldg(&bout[0]);
        __syncthreads();
    }
}

extern "C" void kernel_launch(void* const* d_in, const int* in_sizes, int n_in,
                              void* d_out, int out_size) {
    (void)in_sizes; (void)n_in; (void)out_size;
    const float* inp  = (const float*)d_in[0];
    const void*  slen = (const void*)d_in[1];
    const float* Wx   = (const float*)d_in[2];
    const float* Wh   = (const float*)d_in[3];
    const float* bias = (const float*)d_in[4];
    const float* Wout = (const float*)d_in[5];
    const float* bout = (const float*)d_in[6];
    float*       out  = (float*)d_out;

    static int s_attr_done = 0;
    if (!s_attr_done) {
        cudaFuncSetAttribute(SequenceModelPadded_kernel,
                             cudaFuncAttributeMaxDynamicSharedMemorySize, SMEM_BYTES);
        s_attr_done = 1;
    }
    SequenceModelPadded_kernel<<<NCTA, NTHREADS, SMEM_BYTES>>>(
        inp, slen, Wx, Wh, bias, Wout, bout, out);
}